// round 12
// baseline (speedup 1.0000x reference)
#include <cuda_runtime.h>
#include <math.h>
#include <stdint.h>

#define BB 8
#define NN 2048
#define MM 2048
#define STRIDE 512            /* max sparse entries per row/col in gmem ELL */
#define PAIRS (STRIDE / 2)
#define NITER 100
#define CL 8                  /* CTAs per cluster (= per batch) */
#define SLICE 256             /* rows/cols owned per CTA        */
#define STAGE 16              /* uint4 pair-slots staged per thread per phase */
#define TXB 7168u             /* per-phase incoming: 7 peers x 1KB bulk */

#define KFLOOR 1.9287498479639178e-22f   /* fp32(exp(-50)) */
#define MUV    4.8828125e-4f             /* 1/2048 */
#define EPSDIV 1e-8f

static __device__ __forceinline__ float uaf(unsigned x) { return __uint_as_float(x); }

// ---- static device scratch (no runtime allocations allowed) ----
__device__ uint4 g_rell4[(size_t)BB * PAIRS * NN];   // (j, Ktilde)    row-major ELL
__device__ uint4 g_cell4[(size_t)BB * PAIRS * MM];   // (i, Ktilde)    col-major ELL
__device__ uint4 g_eell4[(size_t)BB * PAIRS * NN];   // (j, Ktilde*d)  row-major ELL (emd)
__device__ int   g_rcnt[BB * NN];
__device__ int   g_ccnt[BB * MM];
__device__ float g_u[BB * NN];
__device__ float g_v[BB * MM];
__device__ float g_accum;

// ---- dynamic SMEM (~144 KB) ----
struct SKm {
    float u[NN];
    float v[MM];
    uint4 bufA[STAGE * 256];   // staged row entries, layout [k][tid]
    uint4 bufB[STAGE * 256];   // staged col entries
    unsigned long long mbu, mbv;
};

// ---- cluster / DSMEM / mbarrier / cp.async helpers ----
static __device__ __forceinline__ uint32_t smem_u32(const void* p) {
    return (uint32_t)__cvta_generic_to_shared(p);
}
static __device__ __forceinline__ uint32_t mapa_sh(uint32_t addr, uint32_t rank) {
    uint32_t o;
    asm("mapa.shared::cluster.u32 %0, %1, %2;" : "=r"(o) : "r"(addr), "r"(rank));
    return o;
}
static __device__ __forceinline__ void bulk_s2s(uint32_t dst_cluster, uint32_t src_cta,
                                                uint32_t bytes, uint32_t dmbar_cluster) {
    asm volatile("cp.async.bulk.shared::cluster.shared::cta.mbarrier::complete_tx::bytes "
                 "[%0], [%1], %2, [%3];"
                 :: "r"(dst_cluster), "r"(src_cta), "r"(bytes), "r"(dmbar_cluster) : "memory");
}
static __device__ __forceinline__ void fence_proxy_async_cta() {
    asm volatile("fence.proxy.async.shared::cta;" ::: "memory");
}
static __device__ __forceinline__ void cp16(uint32_t dst, const void* src, uint32_t nbytes) {
    // stages 16B; zero-fills when nbytes==0 (entry beyond row count)
    asm volatile("cp.async.cg.shared.global [%0], [%1], 16, %2;"
                 :: "r"(dst), "l"(src), "r"(nbytes) : "memory");
}
static __device__ __forceinline__ void cp_commit() {
    asm volatile("cp.async.commit_group;" ::: "memory");
}
static __device__ __forceinline__ void cp_wait_all() {
    asm volatile("cp.async.wait_group 0;" ::: "memory");
}
static __device__ __forceinline__ void mb_init(uint32_t mb, uint32_t cnt) {
    asm volatile("mbarrier.init.shared.b64 [%0], %1;" :: "r"(mb), "r"(cnt) : "memory");
}
static __device__ __forceinline__ void mb_expect(uint32_t mb, uint32_t tx) {
    asm volatile("mbarrier.arrive.expect_tx.shared.b64 _, [%0], %1;" :: "r"(mb), "r"(tx) : "memory");
}
static __device__ __forceinline__ void mb_wait(uint32_t mb, uint32_t parity) {
    uint32_t done;
    asm volatile("{\n\t.reg .pred p;\n\t"
                 "mbarrier.try_wait.parity.acquire.cluster.shared::cta.b64 p, [%1], %2;\n\t"
                 "selp.b32 %0, 1, 0, p;\n\t}"
                 : "=r"(done) : "r"(mb), "r"(parity) : "memory");
    while (!done) {
        asm volatile("{\n\t.reg .pred p;\n\t"
                     "mbarrier.try_wait.parity.acquire.cluster.shared::cta.b64 p, [%1], %2, 0x989680;\n\t"
                     "selp.b32 %0, 1, 0, p;\n\t}"
                     : "=r"(done) : "r"(mb), "r"(parity) : "memory");
    }
}
#define CLUSTER_SYNC() do {                                                 \
    asm volatile("barrier.cluster.arrive.aligned;" ::: "memory");           \
    asm volatile("barrier.cluster.wait.aligned;"   ::: "memory");           \
} while (0)

// ---------------------------------------------------------------------------
__global__ void init_kernel() {
    int t = blockIdx.x * blockDim.x + threadIdx.x;
    if (t < BB * MM) g_ccnt[t] = 0;
    if (t == 0) g_accum = 0.0f;
}

// ---------------------------------------------------------------------------
// Build sparse correction lists where d^2 < 0.25 (100*d < 50); elsewhere
// K == exp(-50) exactly (same bits as the reference clamp).
__global__ void build_kernel(const float* __restrict__ src, const float* __restrict__ tgt) {
    const int b = blockIdx.y;
    __shared__ float tx[MM], ty[MM], tz[MM];
    const float* T = tgt + (size_t)b * MM * 3;
    for (int j = threadIdx.x; j < MM; j += blockDim.x) {
        tx[j] = T[3 * j + 0];
        ty[j] = T[3 * j + 1];
        tz[j] = T[3 * j + 2];
    }
    __syncthreads();

    const int warp = threadIdx.x >> 5, lane = threadIdx.x & 31;
    const int nwarps = blockDim.x >> 5;
    const int rows_per_cta = NN / gridDim.x;
    const int row0 = blockIdx.x * rows_per_cta;
    const float* S = src + (size_t)b * NN * 3;
    uint2* rell2 = (uint2*)(g_rell4 + (size_t)b * PAIRS * NN);
    uint2* eell2 = (uint2*)(g_eell4 + (size_t)b * PAIRS * NN);
    uint2* cell2 = (uint2*)(g_cell4 + (size_t)b * PAIRS * MM);

    for (int i = row0 + warp; i < row0 + rows_per_cta; i += nwarps) {
        const float sx = S[3 * i + 0], sy = S[3 * i + 1], sz = S[3 * i + 2];
        int rbase = 0;
        for (int j0 = 0; j0 < MM; j0 += 32) {
            const int j = j0 + lane;
            float dx = sx - tx[j];
            float dy = sy - ty[j];
            float dz = sz - tz[j];
            float s = fmaf(dx, dx, fmaf(dy, dy, dz * dz));
            bool pred = (s < 0.25f);
            unsigned mask = __ballot_sync(0xffffffffu, pred);
            if (pred) {
                float d = sqrtf(s);
                float kt = expf(-100.0f * d) - KFLOOR;
                int k = rbase + __popc(mask & ((1u << lane) - 1u));
                if (k < STRIDE) {
                    size_t i2 = ((size_t)(k >> 1) * NN + i) * 2 + (k & 1);
                    rell2[i2] = make_uint2((unsigned)j, __float_as_uint(kt));
                    eell2[i2] = make_uint2((unsigned)j, __float_as_uint(kt * d));
                }
                int kc = atomicAdd(&g_ccnt[b * MM + j], 1);
                if (kc < STRIDE)
                    cell2[((size_t)(kc >> 1) * MM + j) * 2 + (kc & 1)] =
                        make_uint2((unsigned)i, __float_as_uint(kt));
            }
            rbase += __popc(mask);
        }
        int cap = (rbase < STRIDE) ? rbase : STRIDE;
        if (lane == 0) {
            g_rcnt[b * NN + i] = cap;
            if (cap & 1) {   // zero-pad ELL odd tail (cap==STRIDE is even)
                size_t i2 = ((size_t)(cap >> 1) * NN + i) * 2 + 1;
                rell2[i2] = make_uint2(0u, 0u);
                eell2[i2] = make_uint2(0u, 0u);
            }
        }
    }
}

// Clamp column counts + zero-pad odd tails of the column lists.
__global__ void colfix_kernel() {
    int t = blockIdx.x * blockDim.x + threadIdx.x;
    if (t >= BB * MM) return;
    int c = g_ccnt[t];
    if (c > STRIDE) c = STRIDE;
    g_ccnt[t] = c;
    if (c & 1) {
        int b = t / MM, j = t - b * MM;
        uint2* cell2 = (uint2*)(g_cell4 + (size_t)b * PAIRS * MM);
        cell2[((size_t)(c >> 1) * MM + j) * 2 + 1] = make_uint2(0u, 0u);
    }
}

// ---------------------------------------------------------------------------
// 256 threads/CTA, one thread per owned row+col. Software-pipelined:
// during each phase's mbarrier wait, the NEXT phase's ELL entries are staged
// into SMEM via cp.async (zero-filled past the row count), so post-wait work
// is a fixed 16-slot LDS+FMA loop. Broadcast: 7 parallel 1KB bulk copies.
__global__ void __launch_bounds__(256, 1) __cluster_dims__(CL, 1, 1)
sinkhorn_kernel() {
    extern __shared__ char raw[];
    SKm* S = (SKm*)raw;
    uint32_t crank;
    asm("mov.u32 %0, %%cluster_ctarank;" : "=r"(crank));
    const int b    = blockIdx.x >> 3;
    const int tid  = threadIdx.x;
    const int row0 = (int)crank * SLICE;

    for (int j = tid; j < MM; j += 256) S->v[j] = 1.0f;
    if (tid == 0) {
        mb_init(smem_u32(&S->mbu), 1);
        mb_init(smem_u32(&S->mbv), 1);
    }
    const int rnp = (g_rcnt[b * NN + row0 + tid] + 1) >> 1;   // uint4 pair slots
    const int cnp = (g_ccnt[b * MM + row0 + tid] + 1) >> 1;

    const uint4* prow = g_rell4 + (size_t)b * PAIRS * NN + (row0 + tid);
    const uint4* pcol = g_cell4 + (size_t)b * PAIRS * MM + (row0 + tid);
    const uint32_t mbu = smem_u32(&S->mbu), mbv = smem_u32(&S->mbv);
    const uint32_t uslice = smem_u32(S->u) + (uint32_t)row0 * 4u;
    const uint32_t vslice = smem_u32(S->v) + (uint32_t)row0 * 4u;
    const uint32_t bufAb = smem_u32(S->bufA) + (uint32_t)tid * 16u;
    const uint32_t bufBb = smem_u32(S->bufB) + (uint32_t)tid * 16u;
    // sender threads 32..38 -> peer ranks (skip own)
    const bool is_sender = (tid >= 32 && tid < 39);
    uint32_t peer = 0;
    if (is_sender) {
        peer = (uint32_t)(tid - 32);
        if (peer >= crank) peer += 1;
    }

    // preload: stage phase-A row entries into bufA
#pragma unroll
    for (int k = 0; k < STAGE; k++)
        cp16(bufAb + (uint32_t)k * 4096u, prow + (size_t)k * NN, (k < rnp) ? 16u : 0u);
    cp_commit();
    CLUSTER_SYNC();   // v init + peers' mbarriers live before any bulk lands

    for (int iter = 0; iter < NITER; iter++) {
        const uint32_t par = (uint32_t)(iter & 1);

        // ---- phase A: u from v ----
        if (tid == 0) mb_expect(mbu, TXB);
        cp_wait_all();   // bufA staged
        {
            float a0 = 0.0f, a1 = 0.0f;
            const uint4* bA = S->bufA + tid;
#pragma unroll
            for (int k = 0; k < STAGE; k++) {
                uint4 e = bA[k * 256];
                a0 = fmaf(uaf(e.y), S->v[e.x], a0);
                a1 = fmaf(uaf(e.w), S->v[e.z], a1);
            }
            for (int pk = STAGE; pk < rnp; pk += 2) {   // rare heavy-row tail
                uint4 e = prow[(size_t)pk * NN];
                a0 = fmaf(uaf(e.y), S->v[e.x], a0);
                a1 = fmaf(uaf(e.w), S->v[e.z], a1);
                if (pk + 1 < rnp) {
                    uint4 e2 = prow[(size_t)(pk + 1) * NN];
                    a0 = fmaf(uaf(e2.y), S->v[e2.x], a0);
                    a1 = fmaf(uaf(e2.w), S->v[e2.z], a1);
                }
            }
            // KFLOOR*S_v <= 2e-14 is absorbed by the 1e-8 clamp; drop it.
            S->u[row0 + tid] = __fdividef(MUV, fmaxf(a0 + a1, EPSDIV));
        }
        __syncthreads();   // local u slice complete + visible
        if (is_sender) {   // 7 parallel bulk dispatches
            fence_proxy_async_cta();
            bulk_s2s(mapa_sh(uslice, peer), uslice, (uint32_t)SLICE * 4u,
                     mapa_sh(mbu, peer));
        }
        // stage phase-B col entries during the wait
#pragma unroll
        for (int k = 0; k < STAGE; k++)
            cp16(bufBb + (uint32_t)k * 4096u, pcol + (size_t)k * MM, (k < cnp) ? 16u : 0u);
        cp_commit();
        mb_wait(mbu, par);   // acquire: all 7 peer u slices landed

        // ---- phase B: v from u ----
        if (tid == 0) mb_expect(mbv, TXB);
        cp_wait_all();   // bufB staged
        {
            float a0 = 0.0f, a1 = 0.0f;
            const uint4* bB = S->bufB + tid;
#pragma unroll
            for (int k = 0; k < STAGE; k++) {
                uint4 e = bB[k * 256];
                a0 = fmaf(uaf(e.y), S->u[e.x], a0);
                a1 = fmaf(uaf(e.w), S->u[e.z], a1);
            }
            for (int pk = STAGE; pk < cnp; pk += 2) {
                uint4 e = pcol[(size_t)pk * MM];
                a0 = fmaf(uaf(e.y), S->u[e.x], a0);
                a1 = fmaf(uaf(e.w), S->u[e.z], a1);
                if (pk + 1 < cnp) {
                    uint4 e2 = pcol[(size_t)(pk + 1) * MM];
                    a0 = fmaf(uaf(e2.y), S->u[e2.x], a0);
                    a1 = fmaf(uaf(e2.w), S->u[e2.z], a1);
                }
            }
            S->v[row0 + tid] = __fdividef(MUV, fmaxf(a0 + a1, EPSDIV));
        }
        __syncthreads();
        if (is_sender) {
            fence_proxy_async_cta();
            bulk_s2s(mapa_sh(vslice, peer), vslice, (uint32_t)SLICE * 4u,
                     mapa_sh(mbv, peer));
        }
        // stage next phase-A row entries during the wait
#pragma unroll
        for (int k = 0; k < STAGE; k++)
            cp16(bufAb + (uint32_t)k * 4096u, prow + (size_t)k * NN, (k < rnp) ? 16u : 0u);
        cp_commit();
        mb_wait(mbv, par);
    }

    g_u[b * NN + row0 + tid] = S->u[row0 + tid];
    g_v[b * MM + row0 + tid] = S->v[row0 + tid];
    cp_wait_all();
    CLUSTER_SYNC();   // all final-epoch bulk traffic delivered before exit
}

// ---------------------------------------------------------------------------
// emd_b = sum_i u_i * ( KFLOOR * sum_j d_ij v_j + sum_sparse (K~ d)_ij v_j )
__global__ void emd_kernel(const float* __restrict__ src, const float* __restrict__ tgt) {
    const int b = blockIdx.y;
    __shared__ float tx[MM], ty[MM], tz[MM], vv[MM];
    __shared__ float redw[8];
    const float* T = tgt + (size_t)b * MM * 3;
    for (int j = threadIdx.x; j < MM; j += blockDim.x) {
        tx[j] = T[3 * j + 0];
        ty[j] = T[3 * j + 1];
        tz[j] = T[3 * j + 2];
        vv[j] = g_v[b * MM + j];
    }
    __syncthreads();

    const int warp = threadIdx.x >> 5, lane = threadIdx.x & 31;
    const int nwarps = blockDim.x >> 5;
    const int rows_per_cta = NN / gridDim.x;
    const int row0 = blockIdx.x * rows_per_cta;
    const float* S = src + (size_t)b * NN * 3;
    const uint4* eell = g_eell4 + (size_t)b * PAIRS * NN;

    float wacc = 0.0f;
    for (int i = row0 + warp; i < row0 + rows_per_cta; i += nwarps) {
        const float sx = S[3 * i + 0], sy = S[3 * i + 1], sz = S[3 * i + 2];
        const float ui = g_u[b * NN + i];
        float dacc = 0.0f;
        for (int j0 = 0; j0 < MM; j0 += 32) {
            const int j = j0 + lane;
            float dx = sx - tx[j];
            float dy = sy - ty[j];
            float dz = sz - tz[j];
            float s = fmaf(dx, dx, fmaf(dy, dy, dz * dz));
            dacc = fmaf(sqrtf(s), vv[j], dacc);
        }
        float sacc = 0.0f;
        const int np = (g_rcnt[b * NN + i] + 1) >> 1;
        const uint4* p = eell + i;
        for (int pp = lane; pp < np; pp += 32) {
            uint4 e = p[(size_t)pp * NN];
            sacc = fmaf(uaf(e.y), vv[e.x], sacc);
            sacc = fmaf(uaf(e.w), vv[e.z], sacc);
        }
        float tot = fmaf(KFLOOR, dacc, sacc);
#pragma unroll
        for (int o = 16; o > 0; o >>= 1) tot += __shfl_xor_sync(0xffffffffu, tot, o);
        if (lane == 0) wacc = fmaf(ui, tot, wacc);
    }
    if (lane == 0) redw[warp] = wacc;
    __syncthreads();
    if (threadIdx.x == 0) {
        float s = 0.0f;
        for (int w = 0; w < nwarps; w++) s += redw[w];
        atomicAdd(&g_accum, s);
    }
}

__global__ void finalize_kernel(float* out) { out[0] = g_accum * (1.0f / BB); }

// ---------------------------------------------------------------------------
extern "C" void kernel_launch(void* const* d_in, const int* in_sizes, int n_in,
                              void* d_out, int out_size) {
    (void)in_sizes; (void)n_in; (void)out_size;
    const float* src = (const float*)d_in[0];
    const float* tgt = (const float*)d_in[1];
    float* out = (float*)d_out;

    cudaFuncSetAttribute(sinkhorn_kernel, cudaFuncAttributeMaxDynamicSharedMemorySize,
                         (int)sizeof(SKm));

    // 6 launches/call (same shape as R11, whose ncu capture hit sinkhorn).
    init_kernel<<<64, 256>>>();
    build_kernel<<<dim3(64, BB), 256>>>(src, tgt);
    colfix_kernel<<<64, 256>>>();
    sinkhorn_kernel<<<BB * CL, 256, sizeof(SKm)>>>();
    emd_kernel<<<dim3(64, BB), 256>>>(src, tgt);
    finalize_kernel<<<1, 1>>>(out);
}

// round 13
// speedup vs baseline: 1.6259x; 1.6259x over previous
#include <cuda_runtime.h>
#include <math.h>
#include <stdint.h>

#define BB 8
#define NN 2048
#define MM 2048
#define STRIDE 512            /* max sparse entries per row/col in gmem ELL */
#define PAIRS (STRIDE / 2)
#define NITER 100
#define CL 8                  /* CTAs per cluster (= per batch) */
#define SLICE 256             /* rows/cols owned per CTA        */
#define RSTAGE 22             /* pair slots per thread resident in SMEM     */
#define TXB 8192u             /* per-phase incoming: 8 ranks x 256 x 4B (incl. self) */

#define KFLOOR 1.9287498479639178e-22f   /* fp32(exp(-50)) */
#define MUV    4.8828125e-4f             /* 1/2048 */
#define EPSDIV 1e-8f

static __device__ __forceinline__ float uaf(unsigned x) { return __uint_as_float(x); }

// ---- static device scratch (no runtime allocations allowed) ----
__device__ uint4 g_rell4[(size_t)BB * PAIRS * NN];   // (j, Ktilde)    row-major ELL
__device__ uint4 g_cell4[(size_t)BB * PAIRS * MM];   // (i, Ktilde)    col-major ELL
__device__ uint4 g_eell4[(size_t)BB * PAIRS * NN];   // (j, Ktilde*d)  row-major ELL (emd)
__device__ int   g_rcnt[BB * NN];
__device__ int   g_ccnt[BB * MM];
__device__ float g_u[BB * NN];
__device__ float g_v[BB * MM];
__device__ float g_accum;

// ---- dynamic SMEM (~197 KB) ----
struct SKm {
    float u[NN];
    float v[MM];
    uint4 bufR[RSTAGE * 256];   // resident row entries, layout [k][tid]
    uint4 bufC[RSTAGE * 256];   // resident col entries
    unsigned long long mbu, mbv;
};

// ---- cluster / DSMEM / mbarrier helpers ----
static __device__ __forceinline__ uint32_t smem_u32(const void* p) {
    return (uint32_t)__cvta_generic_to_shared(p);
}
static __device__ __forceinline__ uint32_t mapa_sh(uint32_t addr, uint32_t rank) {
    uint32_t o;
    asm("mapa.shared::cluster.u32 %0, %1, %2;" : "=r"(o) : "r"(addr), "r"(rank));
    return o;
}
static __device__ __forceinline__ void st_async64(uint32_t daddr, unsigned long long v, uint32_t dmbar) {
    asm volatile("st.async.shared::cluster.mbarrier::complete_tx::bytes.u64 [%0], %1, [%2];"
                 :: "r"(daddr), "l"(v), "r"(dmbar) : "memory");
}
static __device__ __forceinline__ void mb_init(uint32_t mb, uint32_t cnt) {
    asm volatile("mbarrier.init.shared.b64 [%0], %1;" :: "r"(mb), "r"(cnt) : "memory");
}
static __device__ __forceinline__ void mb_expect(uint32_t mb, uint32_t tx) {
    asm volatile("mbarrier.arrive.expect_tx.shared.b64 _, [%0], %1;" :: "r"(mb), "r"(tx) : "memory");
}
static __device__ __forceinline__ void mb_wait(uint32_t mb, uint32_t parity) {
    uint32_t done;
    asm volatile("{\n\t.reg .pred p;\n\t"
                 "mbarrier.try_wait.parity.acquire.cluster.shared::cta.b64 p, [%1], %2;\n\t"
                 "selp.b32 %0, 1, 0, p;\n\t}"
                 : "=r"(done) : "r"(mb), "r"(parity) : "memory");
    while (!done) {
        asm volatile("{\n\t.reg .pred p;\n\t"
                     "mbarrier.try_wait.parity.acquire.cluster.shared::cta.b64 p, [%1], %2, 0x989680;\n\t"
                     "selp.b32 %0, 1, 0, p;\n\t}"
                     : "=r"(done) : "r"(mb), "r"(parity) : "memory");
    }
}
#define CLUSTER_SYNC() do {                                                 \
    asm volatile("barrier.cluster.arrive.aligned;" ::: "memory");           \
    asm volatile("barrier.cluster.wait.aligned;"   ::: "memory");           \
} while (0)

// ---------------------------------------------------------------------------
__global__ void init_kernel() {
    int t = blockIdx.x * blockDim.x + threadIdx.x;
    if (t < BB * MM) g_ccnt[t] = 0;
    if (t == 0) g_accum = 0.0f;
}

// ---------------------------------------------------------------------------
// Build sparse correction lists where d^2 < 0.25 (100*d < 50); elsewhere
// K == exp(-50) exactly (same bits as the reference clamp).
__global__ void build_kernel(const float* __restrict__ src, const float* __restrict__ tgt) {
    const int b = blockIdx.y;
    __shared__ float tx[MM], ty[MM], tz[MM];
    const float* T = tgt + (size_t)b * MM * 3;
    for (int j = threadIdx.x; j < MM; j += blockDim.x) {
        tx[j] = T[3 * j + 0];
        ty[j] = T[3 * j + 1];
        tz[j] = T[3 * j + 2];
    }
    __syncthreads();

    const int warp = threadIdx.x >> 5, lane = threadIdx.x & 31;
    const int nwarps = blockDim.x >> 5;
    const int rows_per_cta = NN / gridDim.x;
    const int row0 = blockIdx.x * rows_per_cta;
    const float* S = src + (size_t)b * NN * 3;
    uint2* rell2 = (uint2*)(g_rell4 + (size_t)b * PAIRS * NN);
    uint2* eell2 = (uint2*)(g_eell4 + (size_t)b * PAIRS * NN);
    uint2* cell2 = (uint2*)(g_cell4 + (size_t)b * PAIRS * MM);

    for (int i = row0 + warp; i < row0 + rows_per_cta; i += nwarps) {
        const float sx = S[3 * i + 0], sy = S[3 * i + 1], sz = S[3 * i + 2];
        int rbase = 0;
        for (int j0 = 0; j0 < MM; j0 += 32) {
            const int j = j0 + lane;
            float dx = sx - tx[j];
            float dy = sy - ty[j];
            float dz = sz - tz[j];
            float s = fmaf(dx, dx, fmaf(dy, dy, dz * dz));
            bool pred = (s < 0.25f);
            unsigned mask = __ballot_sync(0xffffffffu, pred);
            if (pred) {
                float d = sqrtf(s);
                float kt = expf(-100.0f * d) - KFLOOR;
                int k = rbase + __popc(mask & ((1u << lane) - 1u));
                if (k < STRIDE) {
                    size_t i2 = ((size_t)(k >> 1) * NN + i) * 2 + (k & 1);
                    rell2[i2] = make_uint2((unsigned)j, __float_as_uint(kt));
                    eell2[i2] = make_uint2((unsigned)j, __float_as_uint(kt * d));
                }
                int kc = atomicAdd(&g_ccnt[b * MM + j], 1);
                if (kc < STRIDE)
                    cell2[((size_t)(kc >> 1) * MM + j) * 2 + (kc & 1)] =
                        make_uint2((unsigned)i, __float_as_uint(kt));
            }
            rbase += __popc(mask);
        }
        int cap = (rbase < STRIDE) ? rbase : STRIDE;
        if (lane == 0) {
            g_rcnt[b * NN + i] = cap;
            if (cap & 1) {   // zero-pad ELL odd tail (cap==STRIDE is even)
                size_t i2 = ((size_t)(cap >> 1) * NN + i) * 2 + 1;
                rell2[i2] = make_uint2(0u, 0u);
                eell2[i2] = make_uint2(0u, 0u);
            }
        }
    }
}

// Clamp column counts + zero-pad odd tails of the column lists.
__global__ void colfix_kernel() {
    int t = blockIdx.x * blockDim.x + threadIdx.x;
    if (t >= BB * MM) return;
    int c = g_ccnt[t];
    if (c > STRIDE) c = STRIDE;
    g_ccnt[t] = c;
    if (c & 1) {
        int b = t / MM, j = t - b * MM;
        uint2* cell2 = (uint2*)(g_cell4 + (size_t)b * PAIRS * MM);
        cell2[((size_t)(c >> 1) * MM + j) * 2 + 1] = make_uint2(0u, 0u);
    }
}

// ---------------------------------------------------------------------------
// 256 threads/CTA, one thread per owned row+col. ELL entry lists are loaded
// into SMEM ONCE before the loop ([k][tid] layout: LDS.128 conflict-free).
// Phases are barrier-free: gather (SMEM) -> st.async pairs to all 8 ranks
// (incl. self loopback) -> tx-counted mbarrier wait. Same causality chains
// as R9 (rel_err-validated).
__global__ void __launch_bounds__(256, 1) __cluster_dims__(CL, 1, 1)
sinkhorn_kernel() {
    extern __shared__ char raw[];
    SKm* S = (SKm*)raw;
    uint32_t crank;
    asm("mov.u32 %0, %%cluster_ctarank;" : "=r"(crank));
    const int b    = blockIdx.x >> 3;
    const int tid  = threadIdx.x;
    const int row0 = (int)crank * SLICE;

    for (int j = tid; j < MM; j += 256) S->v[j] = 1.0f;
    if (tid == 0) {
        mb_init(smem_u32(&S->mbu), 1);
        mb_init(smem_u32(&S->mbv), 1);
    }
    const int rnp = (g_rcnt[b * NN + row0 + tid] + 1) >> 1;   // uint4 pair slots
    const int cnp = (g_ccnt[b * MM + row0 + tid] + 1) >> 1;

    const uint4* prow = g_rell4 + (size_t)b * PAIRS * NN + (row0 + tid);
    const uint4* pcol = g_cell4 + (size_t)b * PAIRS * MM + (row0 + tid);

    // one-time preload of entry lists into SMEM (coalesced across tid)
    const int rs = (rnp < RSTAGE) ? rnp : RSTAGE;
    const int cs = (cnp < RSTAGE) ? cnp : RSTAGE;
    for (int k = 0; k < rs; k++) S->bufR[k * 256 + tid] = prow[(size_t)k * NN];
    for (int k = 0; k < cs; k++) S->bufC[k * 256 + tid] = pcol[(size_t)k * MM];

    const uint32_t mbu = smem_u32(&S->mbu), mbv = smem_u32(&S->mbv);
    const uint32_t usend = smem_u32(S->u) + (uint32_t)(row0 + (tid & ~1)) * 4u;
    const uint32_t vsend = smem_u32(S->v) + (uint32_t)(row0 + (tid & ~1)) * 4u;
    const bool sender = !(tid & 1);
    const uint4* bR = S->bufR + tid;
    const uint4* bC = S->bufC + tid;

    CLUSTER_SYNC();   // v_sh + peers' mbarriers live before any st.async lands

    for (int iter = 0; iter < NITER; iter++) {
        const uint32_t par = (uint32_t)(iter & 1);

        // ---- phase A: u from v ----
        if (tid == 0) mb_expect(mbu, TXB);
        {
            float a0 = 0.0f, a1 = 0.0f;
#pragma unroll 4
            for (int pk = 0; pk < rs; pk++) {
                uint4 e = bR[pk * 256];
                a0 = fmaf(uaf(e.y), S->v[e.x], a0);
                a1 = fmaf(uaf(e.w), S->v[e.z], a1);
            }
            for (int pk = RSTAGE; pk < rnp; pk++) {   // very rare heavy-row tail
                uint4 e = prow[(size_t)pk * NN];
                a0 = fmaf(uaf(e.y), S->v[e.x], a0);
                a1 = fmaf(uaf(e.w), S->v[e.z], a1);
            }
            // KFLOOR*S_v <= 2e-14 is absorbed by the 1e-8 clamp; drop it.
            float u = __fdividef(MUV, fmaxf(a0 + a1, EPSDIV));
            float u1 = __shfl_down_sync(0xffffffffu, u, 1);
            if (sender) {
                unsigned long long pk2 =
                    ((unsigned long long)__float_as_uint(u1) << 32) | __float_as_uint(u);
#pragma unroll
                for (uint32_t r = 0; r < CL; r++)
                    st_async64(mapa_sh(usend, r), pk2, mapa_sh(mbu, r));
            }
        }
        mb_wait(mbu, par);   // acquire: all 2048 u values (incl. local) visible

        // ---- phase B: v from u ----
        if (tid == 0) mb_expect(mbv, TXB);
        {
            float a0 = 0.0f, a1 = 0.0f;
#pragma unroll 4
            for (int pk = 0; pk < cs; pk++) {
                uint4 e = bC[pk * 256];
                a0 = fmaf(uaf(e.y), S->u[e.x], a0);
                a1 = fmaf(uaf(e.w), S->u[e.z], a1);
            }
            for (int pk = RSTAGE; pk < cnp; pk++) {
                uint4 e = pcol[(size_t)pk * MM];
                a0 = fmaf(uaf(e.y), S->u[e.x], a0);
                a1 = fmaf(uaf(e.w), S->u[e.z], a1);
            }
            float v = __fdividef(MUV, fmaxf(a0 + a1, EPSDIV));
            float v1 = __shfl_down_sync(0xffffffffu, v, 1);
            if (sender) {
                unsigned long long pk2 =
                    ((unsigned long long)__float_as_uint(v1) << 32) | __float_as_uint(v);
#pragma unroll
                for (uint32_t r = 0; r < CL; r++)
                    st_async64(mapa_sh(vsend, r), pk2, mapa_sh(mbv, r));
            }
        }
        mb_wait(mbv, par);
    }

    g_u[b * NN + row0 + tid] = S->u[row0 + tid];
    g_v[b * MM + row0 + tid] = S->v[row0 + tid];
    CLUSTER_SYNC();   // no CTA exits with peer traffic in flight
}

// ---------------------------------------------------------------------------
// emd_b = sum_i u_i * ( KFLOOR * sum_j d_ij v_j + sum_sparse (K~ d)_ij v_j )
__global__ void emd_kernel(const float* __restrict__ src, const float* __restrict__ tgt) {
    const int b = blockIdx.y;
    __shared__ float tx[MM], ty[MM], tz[MM], vv[MM];
    __shared__ float redw[8];
    const float* T = tgt + (size_t)b * MM * 3;
    for (int j = threadIdx.x; j < MM; j += blockDim.x) {
        tx[j] = T[3 * j + 0];
        ty[j] = T[3 * j + 1];
        tz[j] = T[3 * j + 2];
        vv[j] = g_v[b * MM + j];
    }
    __syncthreads();

    const int warp = threadIdx.x >> 5, lane = threadIdx.x & 31;
    const int nwarps = blockDim.x >> 5;
    const int rows_per_cta = NN / gridDim.x;
    const int row0 = blockIdx.x * rows_per_cta;
    const float* S = src + (size_t)b * NN * 3;
    const uint4* eell = g_eell4 + (size_t)b * PAIRS * NN;

    float wacc = 0.0f;
    for (int i = row0 + warp; i < row0 + rows_per_cta; i += nwarps) {
        const float sx = S[3 * i + 0], sy = S[3 * i + 1], sz = S[3 * i + 2];
        const float ui = g_u[b * NN + i];
        float dacc = 0.0f;
        for (int j0 = 0; j0 < MM; j0 += 32) {
            const int j = j0 + lane;
            float dx = sx - tx[j];
            float dy = sy - ty[j];
            float dz = sz - tz[j];
            float s = fmaf(dx, dx, fmaf(dy, dy, dz * dz));
            dacc = fmaf(sqrtf(s), vv[j], dacc);
        }
        float sacc = 0.0f;
        const int np = (g_rcnt[b * NN + i] + 1) >> 1;
        const uint4* p = eell + i;
        for (int pp = lane; pp < np; pp += 32) {
            uint4 e = p[(size_t)pp * NN];
            sacc = fmaf(uaf(e.y), vv[e.x], sacc);
            sacc = fmaf(uaf(e.w), vv[e.z], sacc);
        }
        float tot = fmaf(KFLOOR, dacc, sacc);
#pragma unroll
        for (int o = 16; o > 0; o >>= 1) tot += __shfl_xor_sync(0xffffffffu, tot, o);
        if (lane == 0) wacc = fmaf(ui, tot, wacc);
    }
    if (lane == 0) redw[warp] = wacc;
    __syncthreads();
    if (threadIdx.x == 0) {
        float s = 0.0f;
        for (int w = 0; w < nwarps; w++) s += redw[w];
        atomicAdd(&g_accum, s);
    }
}

__global__ void finalize_kernel(float* out) { out[0] = g_accum * (1.0f / BB); }

// ---------------------------------------------------------------------------
extern "C" void kernel_launch(void* const* d_in, const int* in_sizes, int n_in,
                              void* d_out, int out_size) {
    (void)in_sizes; (void)n_in; (void)out_size;
    const float* src = (const float*)d_in[0];
    const float* tgt = (const float*)d_in[1];
    float* out = (float*)d_out;

    cudaFuncSetAttribute(sinkhorn_kernel, cudaFuncAttributeMaxDynamicSharedMemorySize,
                         (int)sizeof(SKm));

    // 6 launches/call (same shape whose ncu capture hits sinkhorn).
    init_kernel<<<64, 256>>>();
    build_kernel<<<dim3(64, BB), 256>>>(src, tgt);
    colfix_kernel<<<64, 256>>>();
    sinkhorn_kernel<<<BB * CL, 256, sizeof(SKm)>>>();
    emd_kernel<<<dim3(64, BB), 256>>>(src, tgt);
    finalize_kernel<<<1, 1>>>(out);
}